// round 4
// baseline (speedup 1.0000x reference)
#include <cuda_runtime.h>

// MaskedWeight: B=256, DIM=16, H_IN=H_OUT=32, IN_F=OUT_F=512
// Single fused kernel. grid = B*16 CTAs of 256 threads.
// Each warp handles 2 balanced row PAIRS (rb, 15-rb): combined off-diag span
// per pair is always 120 float4 -> fixed fully-unrolled loads, high MLP.
// Per-CTA F2 partial to scratch; the last CTA per sample (atomicInc-wrap
// counter, graph-replay safe) sums partials in fixed order and finalizes.

#define NB 256
#define OUTF 512
#define INF 512
#define SLICES 16

__device__ float g_yraw[NB * OUTF];
__device__ float g_lse[NB * OUTF];
__device__ float g_f2[NB * SLICES];
__device__ unsigned int g_cnt[NB];   // zero-init; self-resets via atomicInc wrap

__global__ __launch_bounds__(256, 6)
void mw_fused(const float* __restrict__ inputs,     // [B, 512]
              const float* __restrict__ hyper_w,    // [B, 512, 512]
              const float* __restrict__ hyper_b,    // [B, 512]
              const float* __restrict__ lgc,        // [B, 16, 32, 1]
              const float* __restrict__ sfp,        // [1]
              float* __restrict__ out)              // [B*512 outputs | B*512 log_det]
{
    const int cta  = blockIdx.x;
    const int b    = cta >> 4;
    const int s    = cta & (SLICES - 1);
    const int tid  = threadIdx.x;
    const int warp = tid >> 5;
    const int lane = tid & 31;
    const int g    = (s << 3) + warp;        // 0..127
    const int colA = g & 31;
    const int rb0  = g >> 5;                 // 0..3

    __shared__ __align__(16) float x_s[INF];
    __shared__ float lgc_s[512];
    __shared__ float f2_red[8];
    __shared__ int amLast;

    x_s[tid]         = inputs[b * INF + tid];
    x_s[tid + 256]   = inputs[b * INF + tid + 256];
    lgc_s[tid]       = lgc[b * 512 + tid];
    lgc_s[tid + 256] = lgc[b * 512 + tid + 256];
    __syncthreads();

    const float*  hw = hyper_w + (size_t)b * (OUTF * INF);
    const float4* x4 = reinterpret_cast<const float4*>(x_s);

    float f2 = 0.0f;

    #pragma unroll
    for (int k = 0; k < 2; k++) {
        const int rbA = rb0 + 4 * k;          // 0..7
        const int rbB = 15 - rbA;             // 15..8
        const int oA  = (rbA << 5) + colA;
        const int oB  = (rbB << 5) + colA;
        const float4* rowA4 = reinterpret_cast<const float4*>(hw + (size_t)oA * INF);
        const float4* rowB4 = reinterpret_cast<const float4*>(hw + (size_t)oB * INF);
        const int n4a = rbA << 3;             // off-diag float4 count of row A (<=56)
        // combined off-diag span = (rbA + rbB)*8 = 120 float4, always.

        float ya = 0.0f, yb = 0.0f;
        #pragma unroll
        for (int j = 0; j < 4; j++) {
            const int i4 = lane + 32 * j;
            if (i4 < 120) {
                const bool inA = (i4 < n4a);
                const int  idx = inA ? i4 : (i4 - n4a);
                const float4 v  = inA ? rowA4[i4] : rowB4[idx];
                const float4 xv = x4[idx];
                float dot = v.x * xv.x;
                dot = fmaf(v.y, xv.y, dot);
                dot = fmaf(v.z, xv.z, dot);
                dot = fmaf(v.w, xv.w, dot);
                f2  = fmaf(v.x, v.x, f2);
                f2  = fmaf(v.y, v.y, f2);
                f2  = fmaf(v.z, v.z, f2);
                f2  = fmaf(v.w, v.w, f2);
                if (inA) ya += dot; else yb += dot;
            }
        }

        // Diagonal blocks: w = exp(hw). lane == hi.
        const int dA = rbA << 5;
        const int dB = rbB << 5;
        const float vA = (hw + (size_t)oA * INF)[dA + lane];
        const float vB = (hw + (size_t)oB * INF)[dB + lane];
        const float eA = __expf(vA);
        const float eB = __expf(vB);
        ya = fmaf(eA, x_s[dA + lane], ya);
        yb = fmaf(eB, x_s[dB + lane], yb);
        f2 = fmaf(eA, eA, f2);
        f2 = fmaf(eB, eB, f2);

        // logsumexp over hi of (hw_diag + lgc[d, hi]) for both rows
        float tA = vA + lgc_s[dA + lane];
        float tB = vB + lgc_s[dB + lane];

        #pragma unroll
        for (int sh = 16; sh; sh >>= 1) {
            ya += __shfl_xor_sync(0xffffffffu, ya, sh);
            yb += __shfl_xor_sync(0xffffffffu, yb, sh);
        }
        float mA = tA, mB = tB;
        #pragma unroll
        for (int sh = 16; sh; sh >>= 1) {
            mA = fmaxf(mA, __shfl_xor_sync(0xffffffffu, mA, sh));
            mB = fmaxf(mB, __shfl_xor_sync(0xffffffffu, mB, sh));
        }
        float sA = __expf(tA - mA);
        float sB = __expf(tB - mB);
        #pragma unroll
        for (int sh = 16; sh; sh >>= 1) {
            sA += __shfl_xor_sync(0xffffffffu, sA, sh);
            sB += __shfl_xor_sync(0xffffffffu, sB, sh);
        }

        if (lane == 0) {
            g_yraw[b * OUTF + oA] = ya;
            g_lse [b * OUTF + oA] = mA + __logf(sA);
        } else if (lane == 1) {
            g_yraw[b * OUTF + oB] = yb;
            g_lse [b * OUTF + oB] = mB + __logf(sB);
        }
    }

    // per-CTA Frobenius partial (fixed slot -> deterministic final sum)
    #pragma unroll
    for (int sh = 16; sh; sh >>= 1) f2 += __shfl_xor_sync(0xffffffffu, f2, sh);
    if (lane == 0) f2_red[warp] = f2;
    __syncthreads();
    if (tid == 0) {
        float t = 0.0f;
        #pragma unroll
        for (int w = 0; w < 8; w++) t += f2_red[w];
        g_f2[b * SLICES + s] = t;
    }

    // ---- last-CTA-per-sample finalize ----
    __threadfence();
    __syncthreads();
    if (tid == 0) {
        unsigned int old = atomicInc(&g_cnt[b], SLICES - 1);  // wraps to 0 on last
        amLast = (old == SLICES - 1);
    }
    __syncthreads();
    if (!amLast) return;
    __threadfence();

    float F2 = 0.0f;
    #pragma unroll
    for (int i = 0; i < SLICES; i++) F2 += g_f2[b * SLICES + i];

    const float sf   = sfp[0];
    const float inv  = __expf(sf) * rsqrtf(F2);
    const float base = sf - 0.5f * __logf(F2);

    #pragma unroll
    for (int r = 0; r < 2; r++) {
        const int o = tid + 256 * r;
        out[b * OUTF + o] = fmaf(g_yraw[b * OUTF + o], inv, hyper_b[b * OUTF + o]);
        out[NB * OUTF + b * 512 + o] = base + g_lse[b * 512 + o];
    }
}

extern "C" void kernel_launch(void* const* d_in, const int* in_sizes, int n_in,
                              void* d_out, int out_size) {
    const float* inputs  = (const float*)d_in[0];
    const float* hyper_w = (const float*)d_in[1];
    const float* hyper_b = (const float*)d_in[2];
    const float* lgc     = (const float*)d_in[3];
    const float* sf      = (const float*)d_in[4];
    mw_fused<<<NB * SLICES, 256>>>(inputs, hyper_w, hyper_b, lgc, sf, (float*)d_out);
}

// round 5
// speedup vs baseline: 1.0265x; 1.0265x over previous
#include <cuda_runtime.h>

// MaskedWeight: B=256, DIM=16, H_IN=H_OUT=32, IN_F=OUT_F=512
// grid = B*8 CTAs x 256 thr. Each warp: 4 balanced row pairs (rb, 15-rb),
// software-pipelined loads (2 pair buffers -> 8 LDG.128 in flight), all
// warp reductions deferred to one interleaved tail. Last CTA per sample
// (atomicInc-wrap, graph-safe) finalizes outputs + log_det.

#define NB 256
#define OUTF 512
#define INF 512
#define SLICES 8

__device__ float g_yraw[NB * OUTF];
__device__ float g_lse[NB * OUTF];
__device__ float g_f2[NB * SLICES];
__device__ unsigned int g_cnt[NB];   // zero-init; self-resets via atomicInc wrap

__global__ __launch_bounds__(256, 3)
void mw_fused(const float* __restrict__ inputs,     // [B, 512]
              const float* __restrict__ hyper_w,    // [B, 512, 512]
              const float* __restrict__ hyper_b,    // [B, 512]
              const float* __restrict__ lgc,        // [B, 16, 32, 1]
              const float* __restrict__ sfp,        // [1]
              float* __restrict__ out)              // [B*512 outputs | B*512 log_det]
{
    const int cta  = blockIdx.x;
    const int b    = cta >> 3;
    const int s    = cta & (SLICES - 1);
    const int tid  = threadIdx.x;
    const int warp = tid >> 5;
    const int lane = tid & 31;
    const int g    = (s << 3) + warp;   // 0..63
    const int colA = g & 31;
    const int rb0  = g >> 5;            // 0..1

    __shared__ __align__(16) float x_s[INF];
    __shared__ float lgc_s[512];
    __shared__ float f2_red[8];
    __shared__ int amLast;

    x_s[tid]         = inputs[b * INF + tid];
    x_s[tid + 256]   = inputs[b * INF + tid + 256];
    lgc_s[tid]       = lgc[b * 512 + tid];
    lgc_s[tid + 256] = lgc[b * 512 + tid + 256];
    __syncthreads();

    const float*  hw = hyper_w + (size_t)b * (OUTF * INF);
    const float4* x4 = reinterpret_cast<const float4*>(x_s);

    float f2 = 0.0f;
    float yaA[4], ybA[4], tAr[4], tBr[4];

    float4 v0[4], v1[4];
    float dA0, dB0, dA1, dB1;

    // Load one pair's data (4 predicated LDG.128 + 2 scalar LDG) into regs.
#define LOADP(K, V, DA, DB) do {                                              \
        const int rbA = rb0 + 2 * (K);                                        \
        const int rbB = 15 - rbA;                                             \
        const float* rowA = hw + (size_t)(((rbA) << 5) + colA) * INF;         \
        const float* rowB = hw + (size_t)(((rbB) << 5) + colA) * INF;         \
        const int n4a = rbA << 3;                                             \
        _Pragma("unroll")                                                     \
        for (int j = 0; j < 4; j++) {                                         \
            const int i4 = lane + 32 * j;                                     \
            const float* p = (i4 < n4a) ? rowA : rowB;                        \
            const int idx  = (i4 < n4a) ? i4 : (i4 - n4a);                    \
            float4 t = make_float4(0.f, 0.f, 0.f, 0.f);                       \
            if (i4 < 120) t = reinterpret_cast<const float4*>(p)[idx];        \
            V[j] = t;                                                         \
        }                                                                     \
        DA = rowA[(rbA << 5) + lane];                                         \
        DB = rowB[(rbB << 5) + lane];                                         \
    } while (0)

    // Consume one pair: FMAs only, no warp reductions (deferred).
#define COMPP(K, V, DA, DB) do {                                              \
        const int rbA = rb0 + 2 * (K);                                        \
        const int rbB = 15 - rbA;                                             \
        const int n4a = rbA << 3;                                             \
        float ya = 0.0f, yb = 0.0f;                                           \
        _Pragma("unroll")                                                     \
        for (int j = 0; j < 4; j++) {                                         \
            const int i4 = lane + 32 * j;                                     \
            const bool inA = (i4 < n4a);                                      \
            const int idx  = inA ? i4 : (i4 - n4a);                           \
            const float4 xv = x4[idx];                                        \
            const float4 v  = V[j];                                           \
            float dot = v.x * xv.x;                                           \
            dot = fmaf(v.y, xv.y, dot);                                       \
            dot = fmaf(v.z, xv.z, dot);                                       \
            dot = fmaf(v.w, xv.w, dot);                                       \
            f2 = fmaf(v.x, v.x, f2);                                          \
            f2 = fmaf(v.y, v.y, f2);                                          \
            f2 = fmaf(v.z, v.z, f2);                                          \
            f2 = fmaf(v.w, v.w, f2);                                          \
            if (inA) ya += dot; else yb += dot;                               \
        }                                                                     \
        const int dAc = rbA << 5, dBc = rbB << 5;                             \
        const float eA = __expf(DA), eB = __expf(DB);                         \
        ya = fmaf(eA, x_s[dAc + lane], ya);                                   \
        yb = fmaf(eB, x_s[dBc + lane], yb);                                   \
        f2 = fmaf(eA, eA, f2);                                                \
        f2 = fmaf(eB, eB, f2);                                                \
        yaA[K] = ya; ybA[K] = yb;                                             \
        tAr[K] = DA + lgc_s[dAc + lane];                                      \
        tBr[K] = DB + lgc_s[dBc + lane];                                      \
    } while (0)

    LOADP(0, v0, dA0, dB0);
    LOADP(1, v1, dA1, dB1);
    COMPP(0, v0, dA0, dB0);
    LOADP(2, v0, dA0, dB0);
    COMPP(1, v1, dA1, dB1);
    LOADP(3, v1, dA1, dB1);
    COMPP(2, v0, dA0, dB0);
    COMPP(3, v1, dA1, dB1);

#undef LOADP
#undef COMPP

    // ---- deferred warp reductions, interleaved across the 4 pairs ----
    #pragma unroll
    for (int sh = 16; sh; sh >>= 1) {
        #pragma unroll
        for (int k = 0; k < 4; k++) {
            yaA[k] += __shfl_xor_sync(0xffffffffu, yaA[k], sh);
            ybA[k] += __shfl_xor_sync(0xffffffffu, ybA[k], sh);
        }
    }
    float mA[4], mB[4];
    #pragma unroll
    for (int k = 0; k < 4; k++) { mA[k] = tAr[k]; mB[k] = tBr[k]; }
    #pragma unroll
    for (int sh = 16; sh; sh >>= 1) {
        #pragma unroll
        for (int k = 0; k < 4; k++) {
            mA[k] = fmaxf(mA[k], __shfl_xor_sync(0xffffffffu, mA[k], sh));
            mB[k] = fmaxf(mB[k], __shfl_xor_sync(0xffffffffu, mB[k], sh));
        }
    }
    float sA[4], sB[4];
    #pragma unroll
    for (int k = 0; k < 4; k++) {
        sA[k] = __expf(tAr[k] - mA[k]);
        sB[k] = __expf(tBr[k] - mB[k]);
    }
    #pragma unroll
    for (int sh = 16; sh; sh >>= 1) {
        #pragma unroll
        for (int k = 0; k < 4; k++) {
            sA[k] += __shfl_xor_sync(0xffffffffu, sA[k], sh);
            sB[k] += __shfl_xor_sync(0xffffffffu, sB[k], sh);
        }
    }

    #pragma unroll
    for (int k = 0; k < 4; k++) {
        const int rbA = rb0 + 2 * k;
        const int oA  = (rbA << 5) + colA;
        const int oB  = ((15 - rbA) << 5) + colA;
        if (lane == 0) {
            g_yraw[b * OUTF + oA] = yaA[k];
            g_lse [b * OUTF + oA] = mA[k] + __logf(sA[k]);
        } else if (lane == 1) {
            g_yraw[b * OUTF + oB] = ybA[k];
            g_lse [b * OUTF + oB] = mB[k] + __logf(sB[k]);
        }
    }

    // per-CTA Frobenius partial (fixed slot -> deterministic final sum)
    #pragma unroll
    for (int sh = 16; sh; sh >>= 1) f2 += __shfl_xor_sync(0xffffffffu, f2, sh);
    if (lane == 0) f2_red[warp] = f2;
    __syncthreads();
    if (tid == 0) {
        float t = 0.0f;
        #pragma unroll
        for (int w = 0; w < 8; w++) t += f2_red[w];
        g_f2[b * SLICES + s] = t;
    }

    // ---- last-CTA-per-sample finalize ----
    __threadfence();
    __syncthreads();
    if (tid == 0) {
        unsigned int old = atomicInc(&g_cnt[b], SLICES - 1);  // wraps to 0 on last
        amLast = (old == SLICES - 1);
    }
    __syncthreads();
    if (!amLast) return;
    __threadfence();

    float F2 = 0.0f;
    #pragma unroll
    for (int i = 0; i < SLICES; i++) F2 += g_f2[b * SLICES + i];

    const float sf   = sfp[0];
    const float inv  = __expf(sf) * rsqrtf(F2);
    const float base = sf - 0.5f * __logf(F2);

    #pragma unroll
    for (int r = 0; r < 2; r++) {
        const int o = tid + 256 * r;
        out[b * OUTF + o] = fmaf(g_yraw[b * OUTF + o], inv, hyper_b[b * OUTF + o]);
        out[NB * OUTF + b * 512 + o] = base + g_lse[b * 512 + o];
    }
}

extern "C" void kernel_launch(void* const* d_in, const int* in_sizes, int n_in,
                              void* d_out, int out_size) {
    const float* inputs  = (const float*)d_in[0];
    const float* hyper_w = (const float*)d_in[1];
    const float* hyper_b = (const float*)d_in[2];
    const float* lgc     = (const float*)d_in[3];
    const float* sf      = (const float*)d_in[4];
    mw_fused<<<NB * SLICES, 256>>>(inputs, hyper_w, hyper_b, lgc, sf, (float*)d_out);
}

// round 7
// speedup vs baseline: 1.1259x; 1.0967x over previous
#include <cuda_runtime.h>

// MaskedWeight: B=256, DIM=16, H_IN=H_OUT=32, IN_F=OUT_F=512
// grid = B*8 CTAs x 256 thr, target 4 CTAs/SM (<=64 regs).
// Each warp: 4 balanced row pairs (rb, 15-rb), 2-deep load pipeline,
// inline per-pair reductions (interleaved chains), max-free logsumexp.
// Last CTA per sample (atomicInc-wrap, graph-safe) finalizes.

#define NB 256
#define OUTF 512
#define INF 512
#define SLICES 8

__device__ float g_yraw[NB * OUTF];
__device__ float g_lse[NB * OUTF];
__device__ float g_f2[NB * SLICES];
__device__ unsigned int g_cnt[NB];   // zero-init; self-resets via atomicInc wrap

__global__ __launch_bounds__(256, 4)
void mw_fused(const float* __restrict__ inputs,     // [B, 512]
              const float* __restrict__ hyper_w,    // [B, 512, 512]
              const float* __restrict__ hyper_b,    // [B, 512]
              const float* __restrict__ lgc,        // [B, 16, 32, 1]
              const float* __restrict__ sfp,        // [1]
              float* __restrict__ out)              // [B*512 outputs | B*512 log_det]
{
    const int cta  = blockIdx.x;
    const int b    = cta >> 3;
    const int s    = cta & (SLICES - 1);
    const int tid  = threadIdx.x;
    const int warp = tid >> 5;
    const int lane = tid & 31;
    const int g    = (s << 3) + warp;   // 0..63
    const int colA = g & 31;
    const int rb0  = g >> 5;            // 0..1

    __shared__ __align__(16) float x_s[INF];
    __shared__ float lgc_s[512];
    __shared__ float f2_red[8];
    __shared__ int amLast;

    x_s[tid]         = inputs[b * INF + tid];
    x_s[tid + 256]   = inputs[b * INF + tid + 256];
    lgc_s[tid]       = lgc[b * 512 + tid];
    lgc_s[tid + 256] = lgc[b * 512 + tid + 256];
    __syncthreads();

    const float*  hw = hyper_w + (size_t)b * (OUTF * INF);
    const float4* x4 = reinterpret_cast<const float4*>(x_s);

    float f2 = 0.0f;

    float4 v0[4], v1[4];
    float dA0, dB0, dA1, dB1;

    // Load one pair's data (4 predicated LDG.128 + 2 scalar LDG) into regs.
#define LOADP(K, V, DA, DB) do {                                              \
        const int rbA = rb0 + 2 * (K);                                        \
        const int rbB = 15 - rbA;                                             \
        const float* rowA = hw + (size_t)(((rbA) << 5) + colA) * INF;         \
        const float* rowB = hw + (size_t)(((rbB) << 5) + colA) * INF;         \
        const int n4a = rbA << 3;                                             \
        _Pragma("unroll")                                                     \
        for (int j = 0; j < 4; j++) {                                         \
            const int i4 = lane + 32 * j;                                     \
            const float* p = (i4 < n4a) ? rowA : rowB;                        \
            const int idx  = (i4 < n4a) ? i4 : (i4 - n4a);                    \
            float4 t = make_float4(0.f, 0.f, 0.f, 0.f);                       \
            if (i4 < 120) t = reinterpret_cast<const float4*>(p)[idx];        \
            V[j] = t;                                                         \
        }                                                                     \
        DA = rowA[(rbA << 5) + lane];                                         \
        DB = rowB[(rbB << 5) + lane];                                         \
    } while (0)

    // Consume one pair: FMAs + inline interleaved warp reductions + store.
#define PROCP(K, V, DA, DB) do {                                              \
        const int rbA = rb0 + 2 * (K);                                        \
        const int rbB = 15 - rbA;                                             \
        const int n4a = rbA << 3;                                             \
        float ya = 0.0f, yb = 0.0f;                                           \
        _Pragma("unroll")                                                     \
        for (int j = 0; j < 4; j++) {                                         \
            const int i4 = lane + 32 * j;                                     \
            const bool inA = (i4 < n4a);                                      \
            const int idx  = inA ? i4 : (i4 - n4a);                           \
            const float4 xv = x4[idx];                                        \
            const float4 v  = V[j];                                           \
            float dot = v.x * xv.x;                                           \
            dot = fmaf(v.y, xv.y, dot);                                       \
            dot = fmaf(v.z, xv.z, dot);                                       \
            dot = fmaf(v.w, xv.w, dot);                                       \
            f2 = fmaf(v.x, v.x, f2);                                          \
            f2 = fmaf(v.y, v.y, f2);                                          \
            f2 = fmaf(v.z, v.z, f2);                                          \
            f2 = fmaf(v.w, v.w, f2);                                          \
            if (inA) ya += dot; else yb += dot;                               \
        }                                                                     \
        const int dAc = rbA << 5, dBc = rbB << 5;                             \
        const float eA = __expf(DA), eB = __expf(DB);                         \
        ya = fmaf(eA, x_s[dAc + lane], ya);                                   \
        yb = fmaf(eB, x_s[dBc + lane], yb);                                   \
        f2 = fmaf(eA, eA, f2);                                                \
        f2 = fmaf(eB, eB, f2);                                                \
        /* max-free logsumexp: values are O(1), fp32-safe */                  \
        float sA = __expf(DA + lgc_s[dAc + lane]);                            \
        float sB = __expf(DB + lgc_s[dBc + lane]);                            \
        _Pragma("unroll")                                                     \
        for (int sh = 16; sh; sh >>= 1) {                                     \
            ya += __shfl_xor_sync(0xffffffffu, ya, sh);                       \
            yb += __shfl_xor_sync(0xffffffffu, yb, sh);                       \
            sA += __shfl_xor_sync(0xffffffffu, sA, sh);                       \
            sB += __shfl_xor_sync(0xffffffffu, sB, sh);                       \
        }                                                                     \
        if (lane == 0) {                                                      \
            const int oA = dAc + colA;                                        \
            g_yraw[b * OUTF + oA] = ya;                                       \
            g_lse [b * OUTF + oA] = __logf(sA);                               \
        } else if (lane == 1) {                                               \
            const int oB = dBc + colA;                                        \
            g_yraw[b * OUTF + oB] = yb;                                       \
            g_lse [b * OUTF + oB] = __logf(sB);                               \
        }                                                                     \
    } while (0)

    LOADP(0, v0, dA0, dB0);
    LOADP(1, v1, dA1, dB1);
    PROCP(0, v0, dA0, dB0);
    LOADP(2, v0, dA0, dB0);
    PROCP(1, v1, dA1, dB1);
    LOADP(3, v1, dA1, dB1);
    PROCP(2, v0, dA0, dB0);
    PROCP(3, v1, dA1, dB1);

#undef LOADP
#undef PROCP

    // per-CTA Frobenius partial (fixed slot -> deterministic final sum)
    #pragma unroll
    for (int sh = 16; sh; sh >>= 1) f2 += __shfl_xor_sync(0xffffffffu, f2, sh);
    if (lane == 0) f2_red[warp] = f2;
    __syncthreads();
    if (tid == 0) {
        float t = 0.0f;
        #pragma unroll
        for (int w = 0; w < 8; w++) t += f2_red[w];
        g_f2[b * SLICES + s] = t;
    }

    // ---- last-CTA-per-sample finalize ----
    __threadfence();
    __syncthreads();
    if (tid == 0) {
        unsigned int old = atomicInc(&g_cnt[b], SLICES - 1);  // wraps to 0 on last
        amLast = (old == SLICES - 1);
    }
    __syncthreads();
    if (!amLast) return;
    __threadfence();

    float F2 = 0.0f;
    #pragma unroll
    for (int i = 0; i < SLICES; i++) F2 += g_f2[b * SLICES + i];

    const float sf   = sfp[0];
    const float inv  = __expf(sf) * rsqrtf(F2);
    const float base = sf - 0.5f * __logf(F2);

    #pragma unroll
    for (int r = 0; r < 2; r++) {
        const int o = tid + 256 * r;
        out[b * OUTF + o] = fmaf(g_yraw[b * OUTF + o], inv, hyper_b[b * OUTF + o]);
        out[NB * OUTF + b * 512 + o] = base + g_lse[b * 512 + o];
    }
}

extern "C" void kernel_launch(void* const* d_in, const int* in_sizes, int n_in,
                              void* d_out, int out_size) {
    const float* inputs  = (const float*)d_in[0];
    const float* hyper_w = (const float*)d_in[1];
    const float* hyper_b = (const float*)d_in[2];
    const float* lgc     = (const float*)d_in[3];
    const float* sf      = (const float*)d_in[4];
    mw_fused<<<NB * SLICES, 256>>>(inputs, hyper_w, hyper_b, lgc, sf, (float*)d_out);
}